// round 12
// baseline (speedup 1.0000x reference)
#include <cuda_runtime.h>
#include <cuda_fp16.h>
#include <math.h>
#include <stdint.h>

// Problem constants
#define BATCH 8
#define T_SEQ 1024
#define C_EMB 768
#define NH    8
#define HD    96
#define M_ROWS (BATCH * T_SEQ)   // 8192
#define GK    768

// ---------------------------------------------------------------------------
// Scratch: fp16 arrays
// ---------------------------------------------------------------------------
__device__ __half g_xh[(size_t)M_ROWS * C_EMB];
__device__ __half g_w1h[(size_t)3 * C_EMB * C_EMB];
__device__ __half g_w2h[(size_t)C_EMB * C_EMB];
__device__ __half g_qkvh[(size_t)M_ROWS * 3 * C_EMB];
__device__ __half g_atth[(size_t)M_ROWS * C_EMB];

// ---------------------------------------------------------------------------
// PTX helpers (baseline ISA at compute_103)
// ---------------------------------------------------------------------------
__device__ __forceinline__ uint32_t smem_u32(const void* p) {
    uint32_t a;
    asm("{ .reg .u64 t; cvta.to.shared.u64 t, %1; cvt.u32.u64 %0, t; }"
        : "=r"(a) : "l"(p));
    return a;
}
__device__ __forceinline__ void mma_f16(
    float& c0, float& c1, float& c2, float& c3,
    uint32_t a0, uint32_t a1, uint32_t a2, uint32_t a3,
    uint32_t b0, uint32_t b1)
{
    asm volatile(
        "mma.sync.aligned.m16n8k16.row.col.f32.f16.f16.f32 "
        "{%0,%1,%2,%3}, {%4,%5,%6,%7}, {%8,%9}, {%0,%1,%2,%3};"
        : "+f"(c0), "+f"(c1), "+f"(c2), "+f"(c3)
        : "r"(a0), "r"(a1), "r"(a2), "r"(a3), "r"(b0), "r"(b1));
}
__device__ __forceinline__ void ldm_x4(
    uint32_t& r0, uint32_t& r1, uint32_t& r2, uint32_t& r3, uint32_t saddr)
{
    asm volatile("ldmatrix.sync.aligned.m8n8.x4.shared.b16 {%0,%1,%2,%3}, [%4];"
        : "=r"(r0), "=r"(r1), "=r"(r2), "=r"(r3) : "r"(saddr));
}
__device__ __forceinline__ void ldm_x4_t(
    uint32_t& r0, uint32_t& r1, uint32_t& r2, uint32_t& r3, uint32_t saddr)
{
    asm volatile("ldmatrix.sync.aligned.m8n8.x4.trans.shared.b16 {%0,%1,%2,%3}, [%4];"
        : "=r"(r0), "=r"(r1), "=r"(r2), "=r"(r3) : "r"(saddr));
}
__device__ __forceinline__ void cp16(uint32_t dst, const void* src) {
    asm volatile("cp.async.cg.shared.global [%0], [%1], 16;"
        :: "r"(dst), "l"(src) : "memory");
}
#define CP_COMMIT() asm volatile("cp.async.commit_group;" ::: "memory")
#define CP_WAIT0()  asm volatile("cp.async.wait_group 0;" ::: "memory")
#define CP_WAIT1()  asm volatile("cp.async.wait_group 1;" ::: "memory")

__device__ __forceinline__ uint32_t pkh(float a, float b) {
    __half2 t = __floats2half2_rn(a, b);
    return *reinterpret_cast<uint32_t*>(&t);
}

// ---------------------------------------------------------------------------
// fp32 -> fp16 convert: all three inputs in one grid-stride kernel
// ---------------------------------------------------------------------------
__global__ void cvt_all(const float* __restrict__ s0, __half* __restrict__ h0, int n0,
                        const float* __restrict__ s1, __half* __restrict__ h1, int n1,
                        const float* __restrict__ s2, __half* __restrict__ h2, int n2)
{
    int total = n0 + n1 + n2;
    int i = blockIdx.x * blockDim.x + threadIdx.x;
    int stride = gridDim.x * blockDim.x;
    for (; i < total; i += stride) {
        const float* s; __half* h; int j;
        if (i < n0)            { s = s0; h = h0; j = i; }
        else if (i < n0 + n1)  { s = s1; h = h1; j = i - n0; }
        else                   { s = s2; h = h2; j = i - n0 - n1; }
        float4 v = ((const float4*)s)[j];
        ((uint2*)h)[j] = make_uint2(pkh(v.x, v.y), pkh(v.z, v.w));
    }
}

// ---------------------------------------------------------------------------
// Single-product fp16 GEMM: C = A * W^T + bias.
// CTA (MT*16) x 128, 128 thr, 4 warps (warp (MT*16) x 32), K chunked 64,
// cp.async double-buffered. Smem row = 144 B, conflict-free ldmatrix.
// ---------------------------------------------------------------------------
#define GEMM_STAGE(MT)  (((MT) * 16 + 128) * 144)
#define GEMM_SMEM(MT)   (2 * GEMM_STAGE(MT))
#define NCHUNK (GK / 64)             // 12

template <bool HALF_OUT, int MT>
__global__ __launch_bounds__(128, 4) void gemm_f16(
    const __half* __restrict__ Ag, const __half* __restrict__ Bg,
    const float* __restrict__ bias,
    float* __restrict__ Cf, __half* __restrict__ Chh, int N)
{
    extern __shared__ char smc[];
    const uint32_t smbase = smem_u32(smc);
    constexpr int GA_B = MT * 16 * 144;
    constexpr int STAGE_B = GEMM_STAGE(MT);

    const int tid  = threadIdx.x;
    const int w    = tid >> 5;
    const int lane = tid & 31;
    const int gr   = lane >> 2;
    const int lc   = lane & 3;
    const int bm   = blockIdx.y * (MT * 16);
    const int bn   = blockIdx.x * 128;

    const uint32_t aoff = (uint32_t)((lane & 15) * 144 + ((lane >> 4) << 4));
    const uint32_t boff = (uint32_t)((w * 32 + ((lane >> 4) << 3) + (lane & 7)) * 144
                                     + (((lane >> 3) & 1) << 4));

    auto issue_chunk = [&](int t, int buf) {
        const uint32_t bb = smbase + (uint32_t)(buf * STAGE_B);
        const int k0 = t * 64;
#pragma unroll
        for (int j = 0; j < MT; j++) {             // A: MT*16 rows x 8 chunks
            int i = tid + 128 * j;
            int r = i >> 3, ck = i & 7;
            cp16(bb + (uint32_t)(r * 144 + ck * 16),
                 Ag + (size_t)(bm + r) * GK + k0 + ck * 8);
        }
#pragma unroll
        for (int j = 0; j < 8; j++) {              // B: 128 rows x 8 chunks
            int i = tid + 128 * j;
            int r = i >> 3, ck = i & 7;
            cp16(bb + GA_B + (uint32_t)(r * 144 + ck * 16),
                 Bg + (size_t)(bn + r) * GK + k0 + ck * 8);
        }
        CP_COMMIT();
    };

    float acc[MT][4][4];
#pragma unroll
    for (int mt = 0; mt < MT; mt++)
#pragma unroll
        for (int nt = 0; nt < 4; nt++)
#pragma unroll
            for (int r = 0; r < 4; r++) acc[mt][nt][r] = 0.f;

    issue_chunk(0, 0);
    issue_chunk(1, 1);

    for (int t = 0; t < NCHUNK; t++) {
        if (t + 1 < NCHUNK) { CP_WAIT1(); } else { CP_WAIT0(); }
        __syncthreads();

        {
            const uint32_t bufb = smbase + (uint32_t)((t & 1) * STAGE_B);
            const uint32_t a_b = bufb + aoff;
            const uint32_t b_b = bufb + GA_B + boff;

#pragma unroll
            for (int ks = 0; ks < 4; ks++) {
                const uint32_t kbb = (uint32_t)(ks * 32);
                uint32_t af[MT][4], bf[4][2];
#pragma unroll
                for (int mt = 0; mt < MT; mt++)
                    ldm_x4(af[mt][0], af[mt][1], af[mt][2], af[mt][3],
                           a_b + (uint32_t)(mt * 2304) + kbb);
#pragma unroll
                for (int p = 0; p < 2; p++)
                    ldm_x4(bf[2 * p][0], bf[2 * p][1], bf[2 * p + 1][0], bf[2 * p + 1][1],
                           b_b + (uint32_t)(p * 2304) + kbb);
#pragma unroll
                for (int mt = 0; mt < MT; mt++)
#pragma unroll
                    for (int nt = 0; nt < 4; nt++)
                        mma_f16(acc[mt][nt][0], acc[mt][nt][1],
                                acc[mt][nt][2], acc[mt][nt][3],
                                af[mt][0], af[mt][1], af[mt][2], af[mt][3],
                                bf[nt][0], bf[nt][1]);
            }
        }
        __syncthreads();
        if (t + 2 < NCHUNK) issue_chunk(t + 2, t & 1);
    }

    // epilogue
#pragma unroll
    for (int nt = 0; nt < 4; nt++) {
        const int col = bn + w * 32 + nt * 8 + lc * 2;
        const float2 bj = *(const float2*)(bias + col);
#pragma unroll
        for (int mt = 0; mt < MT; mt++) {
            const int row0 = bm + mt * 16 + gr;
            float x0 = acc[mt][nt][0] + bj.x, y0 = acc[mt][nt][1] + bj.y;
            float x1 = acc[mt][nt][2] + bj.x, y1 = acc[mt][nt][3] + bj.y;
            if (HALF_OUT) {
                *(uint32_t*)(Chh + (size_t)row0 * N + col) = pkh(x0, y0);
                *(uint32_t*)(Chh + (size_t)(row0 + 8) * N + col) = pkh(x1, y1);
            } else {
                *(float2*)(Cf + (size_t)row0 * N + col) = make_float2(x0, y0);
                *(float2*)(Cf + (size_t)(row0 + 8) * N + col) = make_float2(x1, y1);
            }
        }
    }
}

// ---------------------------------------------------------------------------
// Flash attention, fp16 single-product, BQ=64, 128 thr (4 warps x 16 q-rows).
// cp.async double-buffered 64-token K/V tiles; V row-major + ldmatrix.trans.
// 3 CTAs/SM (smem 53 KB, regs ~140).
// ---------------------------------------------------------------------------
#define FBUF_B (64 * 104 * 2)          // 13312 B per array
#define FSTAGE (2 * FBUF_B)            // K + V = 26624 B
#define FL_SMEM_BYTES (2 * FSTAGE)     // 53248

__global__ __launch_bounds__(128) void flash_f16(
    const __half* __restrict__ qkvh, __half* __restrict__ atth)
{
    extern __shared__ char fsm[];
    const uint32_t smbase = smem_u32(fsm);

    const int qt  = 15 - (int)blockIdx.x;  // heavy tiles first
    const int h   = blockIdx.y;
    const int b   = blockIdx.z;
    const int tid  = threadIdx.x;
    const int w    = tid >> 5;
    const int lane = tid & 31;
    const int gr   = lane >> 2;
    const int lc   = lane & 3;
    const int r0l  = w * 16 + gr;          // local q row A (0..63)
    const int r1l  = r0l + 8;

    const int nkt = qt + 1;
    const float rscale = 0.10206207261596577f;

    auto issue_tile = [&](int kt, int buf) {
        const uint32_t bb = smbase + (uint32_t)(buf * FSTAGE);
        const size_t rowbase = (size_t)(b * T_SEQ + kt * 64);
        const size_t koff = (size_t)C_EMB + h * HD;
        const size_t voff = (size_t)2 * C_EMB + h * HD;
#pragma unroll
        for (int j = 0; j < 6; j++) {              // 64 rows x 12 chunks
            int i = tid + 128 * j;
            int r = i / 12, ck = i % 12;
            const size_t so = (rowbase + r) * (3 * C_EMB) + ck * 8;
            uint32_t d = bb + (uint32_t)(r * 208 + ck * 16);
            cp16(d, qkvh + so + koff);             // K
            cp16(d + FBUF_B, qkvh + so + voff);    // V
        }
        CP_COMMIT();
    };

    issue_tile(0, 0);

    {   // stage Q (fp16) into buf1 region (64 rows x 208 B)
        const uint32_t qb = smbase + FSTAGE;
        const size_t rowbase = (size_t)(b * T_SEQ + qt * 64);
        const size_t qoff = (size_t)h * HD;
#pragma unroll
        for (int j = 0; j < 6; j++) {
            int i = tid + 128 * j;
            int r = i / 12, ck = i % 12;
            const size_t so = (rowbase + r) * (3 * C_EMB) + qoff + ck * 8;
            *(uint4*)(fsm + (qb - smbase) + r * 208 + ck * 16) =
                *(const uint4*)(qkvh + so);
        }
    }
    __syncthreads();

    uint32_t Qf[6][4];
    {
        const uint32_t afl = (uint32_t)((lane & 15) * 208 + ((lane >> 4) << 4));
        const uint32_t qh_b = smbase + FSTAGE + (uint32_t)(w * 16 * 208) + afl;
#pragma unroll
        for (int ks = 0; ks < 6; ks++)
            ldm_x4(Qf[ks][0], Qf[ks][1], Qf[ks][2], Qf[ks][3], qh_b + ks * 32);
    }
    __syncthreads();
    if (nkt > 1) issue_tile(1, 1);

    const uint32_t kfl = (uint32_t)((((lane >> 4) << 3) + (lane & 7)) * 208
                                    + ((lane >> 3) & 1) * 16);
    const uint32_t vfl = (uint32_t)((lane & 15) * 208 + ((lane >> 4) << 4));

    float accO[12][4];
#pragma unroll
    for (int nt = 0; nt < 12; nt++)
#pragma unroll
        for (int r = 0; r < 4; r++) accO[nt][r] = 0.f;
    float m0 = -1e30f, m1 = -1e30f, l0 = 0.f, l1 = 0.f;

    for (int kt = 0; kt < nkt; kt++) {
        if (kt + 1 < nkt) { CP_WAIT1(); } else { CP_WAIT0(); }
        __syncthreads();

        const uint32_t bb = smbase + (uint32_t)((kt & 1) * FSTAGE);
        const uint32_t k_b = bb + kfl;
        const uint32_t v_b = bb + FBUF_B + vfl;

        // ---- S = Q K^T ----
        float accS[8][4];
#pragma unroll
        for (int nt = 0; nt < 8; nt++)
#pragma unroll
            for (int r = 0; r < 4; r++) accS[nt][r] = 0.f;

#pragma unroll
        for (int ks = 0; ks < 6; ks++) {
            const uint32_t kxb = (uint32_t)(ks * 32);
            uint32_t bf[8][2];
#pragma unroll
            for (int p = 0; p < 4; p++)
                ldm_x4(bf[2 * p][0], bf[2 * p][1], bf[2 * p + 1][0], bf[2 * p + 1][1],
                       k_b + (uint32_t)(p * 16 * 208) + kxb);
#pragma unroll
            for (int nt = 0; nt < 8; nt++)
                mma_f16(accS[nt][0], accS[nt][1], accS[nt][2], accS[nt][3],
                        Qf[ks][0], Qf[ks][1], Qf[ks][2], Qf[ks][3],
                        bf[nt][0], bf[nt][1]);
        }

#pragma unroll
        for (int nt = 0; nt < 8; nt++)
#pragma unroll
            for (int r = 0; r < 4; r++) accS[nt][r] *= rscale;

        if (kt == qt) {   // diagonal tile: causal mask
#pragma unroll
            for (int nt = 0; nt < 8; nt++) {
                int c0 = nt * 8 + 2 * lc, c1 = c0 + 1;
                if (c0 > r0l) accS[nt][0] = -1e30f;
                if (c1 > r0l) accS[nt][1] = -1e30f;
                if (c0 > r1l) accS[nt][2] = -1e30f;
                if (c1 > r1l) accS[nt][3] = -1e30f;
            }
        }

        // ---- online softmax ----
        float mx0 = accS[0][0], mx1 = accS[0][2];
#pragma unroll
        for (int nt = 0; nt < 8; nt++) {
            mx0 = fmaxf(mx0, fmaxf(accS[nt][0], accS[nt][1]));
            mx1 = fmaxf(mx1, fmaxf(accS[nt][2], accS[nt][3]));
        }
        mx0 = fmaxf(mx0, __shfl_xor_sync(0xffffffffu, mx0, 1));
        mx0 = fmaxf(mx0, __shfl_xor_sync(0xffffffffu, mx0, 2));
        mx1 = fmaxf(mx1, __shfl_xor_sync(0xffffffffu, mx1, 1));
        mx1 = fmaxf(mx1, __shfl_xor_sync(0xffffffffu, mx1, 2));
        float nm0 = fmaxf(m0, mx0), nm1 = fmaxf(m1, mx1);
        float corr0 = __expf(m0 - nm0), corr1 = __expf(m1 - nm1);
        m0 = nm0; m1 = nm1;

        float rs0 = 0.f, rs1 = 0.f;
        uint32_t aP[4][4];
#pragma unroll
        for (int nt = 0; nt < 8; nt++) {
            float p0 = __expf(accS[nt][0] - m0);
            float p1 = __expf(accS[nt][1] - m0);
            float p2 = __expf(accS[nt][2] - m1);
            float p3 = __expf(accS[nt][3] - m1);
            rs0 += p0 + p1; rs1 += p2 + p3;
            const int i0 = (nt & 1) * 2;
            aP[nt >> 1][i0 + 0] = pkh(p0, p1);
            aP[nt >> 1][i0 + 1] = pkh(p2, p3);
        }
        rs0 += __shfl_xor_sync(0xffffffffu, rs0, 1);
        rs0 += __shfl_xor_sync(0xffffffffu, rs0, 2);
        rs1 += __shfl_xor_sync(0xffffffffu, rs1, 1);
        rs1 += __shfl_xor_sync(0xffffffffu, rs1, 2);
        l0 = l0 * corr0 + rs0;
        l1 = l1 * corr1 + rs1;

#pragma unroll
        for (int nt = 0; nt < 12; nt++) {
            accO[nt][0] *= corr0; accO[nt][1] *= corr0;
            accO[nt][2] *= corr1; accO[nt][3] *= corr1;
        }

        // ---- O += P V ----
#pragma unroll
        for (int kt2 = 0; kt2 < 4; kt2++) {
            const uint32_t toff = (uint32_t)(kt2 * 16 * 208);
            uint32_t a0 = aP[kt2][0], a1 = aP[kt2][1], a2 = aP[kt2][2], a3 = aP[kt2][3];
#pragma unroll
            for (int p = 0; p < 6; p++) {
                uint32_t v0, v1, v2, v3;
                ldm_x4_t(v0, v1, v2, v3, v_b + toff + (uint32_t)(p * 32));
                mma_f16(accO[2*p][0], accO[2*p][1], accO[2*p][2], accO[2*p][3],
                        a0, a1, a2, a3, v0, v1);
                mma_f16(accO[2*p+1][0], accO[2*p+1][1], accO[2*p+1][2], accO[2*p+1][3],
                        a0, a1, a2, a3, v2, v3);
            }
        }
        __syncthreads();
        if (kt + 2 < nkt) issue_tile(kt + 2, kt & 1);
    }

    // ---- epilogue: fp16 att ----
    const float inv0 = 1.f / l0;
    const float inv1 = 1.f / l1;
    const size_t grow0 = (size_t)(b * T_SEQ + qt * 64 + r0l);
    const size_t grow1 = grow0 + 8;
#pragma unroll
    for (int nt = 0; nt < 12; nt++) {
        const int col = h * HD + nt * 8 + 2 * lc;
        *(uint32_t*)(atth + grow0 * C_EMB + col) = pkh(accO[nt][0] * inv0, accO[nt][1] * inv0);
        *(uint32_t*)(atth + grow1 * C_EMB + col) = pkh(accO[nt][2] * inv1, accO[nt][3] * inv1);
    }
}

// ---------------------------------------------------------------------------
// Launch
// ---------------------------------------------------------------------------
extern "C" void kernel_launch(void* const* d_in, const int* in_sizes, int n_in,
                              void* d_out, int out_size)
{
    (void)in_sizes; (void)n_in; (void)out_size;
    const float* x  = (const float*)d_in[0];
    const float* w1 = (const float*)d_in[1];
    const float* b1 = (const float*)d_in[2];
    const float* w2 = (const float*)d_in[3];
    const float* b2 = (const float*)d_in[4];
    float* out = (float*)d_out;

    __half *xh, *w1h, *w2h, *qh, *ah;
    cudaGetSymbolAddress((void**)&xh, g_xh);
    cudaGetSymbolAddress((void**)&w1h, g_w1h);
    cudaGetSymbolAddress((void**)&w2h, g_w2h);
    cudaGetSymbolAddress((void**)&qh, g_qkvh);
    cudaGetSymbolAddress((void**)&ah, g_atth);

    cudaFuncSetAttribute((const void*)gemm_f16<true, 4>,
                         cudaFuncAttributeMaxDynamicSharedMemorySize, GEMM_SMEM(4));
    cudaFuncSetAttribute((const void*)gemm_f16<false, 2>,
                         cudaFuncAttributeMaxDynamicSharedMemorySize, GEMM_SMEM(2));
    cudaFuncSetAttribute((const void*)flash_f16,
                         cudaFuncAttributeMaxDynamicSharedMemorySize, FL_SMEM_BYTES);

    // converts (one kernel)
    cvt_all<<<512, 256>>>(x,  xh,  M_ROWS * C_EMB / 4,
                          w1, w1h, 3 * C_EMB * C_EMB / 4,
                          w2, w2h, C_EMB * C_EMB / 4);

    // QKV projection -> fp16 qkv (64-row M tiles)
    gemm_f16<true, 4><<<dim3(3 * C_EMB / 128, M_ROWS / 64), 128, GEMM_SMEM(4)>>>(
        xh, w1h, b1, nullptr, qh, 3 * C_EMB);

    // Causal attention -> fp16 att (BQ=64, 3 CTAs/SM)
    flash_f16<<<dim3(T_SEQ / 64, NH, BATCH), 128, FL_SMEM_BYTES>>>(qh, ah);

    // Output projection -> fp32 out (32-row M tiles: 1536 CTAs, less tail)
    gemm_f16<false, 2><<<dim3(C_EMB / 128, M_ROWS / 32), 128, GEMM_SMEM(2)>>>(
        ah, w2h, b2, out, nullptr, C_EMB);
}

// round 13
// speedup vs baseline: 1.5065x; 1.5065x over previous
#include <cuda_runtime.h>
#include <cuda_fp16.h>
#include <math.h>
#include <stdint.h>

// Problem constants
#define BATCH 8
#define T_SEQ 1024
#define C_EMB 768
#define NH    8
#define HD    96
#define M_ROWS (BATCH * T_SEQ)   // 8192
#define GK    768

// ---------------------------------------------------------------------------
// Scratch: fp16 arrays
// ---------------------------------------------------------------------------
__device__ __half g_xh[(size_t)M_ROWS * C_EMB];
__device__ __half g_w1h[(size_t)3 * C_EMB * C_EMB];
__device__ __half g_w2h[(size_t)C_EMB * C_EMB];
__device__ __half g_qkvh[(size_t)M_ROWS * 3 * C_EMB];
__device__ __half g_atth[(size_t)M_ROWS * C_EMB];

// ---------------------------------------------------------------------------
// PTX helpers (baseline ISA at compute_103)
// ---------------------------------------------------------------------------
__device__ __forceinline__ uint32_t smem_u32(const void* p) {
    uint32_t a;
    asm("{ .reg .u64 t; cvta.to.shared.u64 t, %1; cvt.u32.u64 %0, t; }"
        : "=r"(a) : "l"(p));
    return a;
}
__device__ __forceinline__ void mma_f16(
    float& c0, float& c1, float& c2, float& c3,
    uint32_t a0, uint32_t a1, uint32_t a2, uint32_t a3,
    uint32_t b0, uint32_t b1)
{
    asm volatile(
        "mma.sync.aligned.m16n8k16.row.col.f32.f16.f16.f32 "
        "{%0,%1,%2,%3}, {%4,%5,%6,%7}, {%8,%9}, {%0,%1,%2,%3};"
        : "+f"(c0), "+f"(c1), "+f"(c2), "+f"(c3)
        : "r"(a0), "r"(a1), "r"(a2), "r"(a3), "r"(b0), "r"(b1));
}
__device__ __forceinline__ void ldm_x4(
    uint32_t& r0, uint32_t& r1, uint32_t& r2, uint32_t& r3, uint32_t saddr)
{
    asm volatile("ldmatrix.sync.aligned.m8n8.x4.shared.b16 {%0,%1,%2,%3}, [%4];"
        : "=r"(r0), "=r"(r1), "=r"(r2), "=r"(r3) : "r"(saddr));
}
__device__ __forceinline__ void ldm_x4_t(
    uint32_t& r0, uint32_t& r1, uint32_t& r2, uint32_t& r3, uint32_t saddr)
{
    asm volatile("ldmatrix.sync.aligned.m8n8.x4.trans.shared.b16 {%0,%1,%2,%3}, [%4];"
        : "=r"(r0), "=r"(r1), "=r"(r2), "=r"(r3) : "r"(saddr));
}
__device__ __forceinline__ void cp16(uint32_t dst, const void* src) {
    asm volatile("cp.async.cg.shared.global [%0], [%1], 16;"
        :: "r"(dst), "l"(src) : "memory");
}
#define CP_COMMIT() asm volatile("cp.async.commit_group;" ::: "memory")
#define CP_WAIT0()  asm volatile("cp.async.wait_group 0;" ::: "memory")
#define CP_WAIT1()  asm volatile("cp.async.wait_group 1;" ::: "memory")

__device__ __forceinline__ uint32_t pkh(float a, float b) {
    __half2 t = __floats2half2_rn(a, b);
    return *reinterpret_cast<uint32_t*>(&t);
}

// ---------------------------------------------------------------------------
// fp32 -> fp16 convert: all three inputs in one grid-stride kernel
// ---------------------------------------------------------------------------
__global__ void cvt_all(const float* __restrict__ s0, __half* __restrict__ h0, int n0,
                        const float* __restrict__ s1, __half* __restrict__ h1, int n1,
                        const float* __restrict__ s2, __half* __restrict__ h2, int n2)
{
    int total = n0 + n1 + n2;
    int i = blockIdx.x * blockDim.x + threadIdx.x;
    int stride = gridDim.x * blockDim.x;
    for (; i < total; i += stride) {
        const float* s; __half* h; int j;
        if (i < n0)            { s = s0; h = h0; j = i; }
        else if (i < n0 + n1)  { s = s1; h = h1; j = i - n0; }
        else                   { s = s2; h = h2; j = i - n0 - n1; }
        float4 v = ((const float4*)s)[j];
        ((uint2*)h)[j] = make_uint2(pkh(v.x, v.y), pkh(v.z, v.w));
    }
}

// ---------------------------------------------------------------------------
// Single-product fp16 GEMM: C = A * W^T + bias.
// CTA 64x128 (128 thr, 4 warps each 64x32), K chunked 64, double-buffered
// cp.async. Smem row stride 72 halves (144 B), conflict-free ldmatrix.
// (R11 configuration — measured 96 us on gemm1.)
// ---------------------------------------------------------------------------
#define GST 72
#define GA_B (64 * GST * 2)          // 9216
#define GB_B (128 * GST * 2)         // 18432
#define STAGE_B (GA_B + GB_B)        // 27648
#define GEMM_SMEM_BYTES (2 * STAGE_B) // 55296
#define NCHUNK (GK / 64)             // 12

template <bool HALF_OUT>
__global__ __launch_bounds__(128, 4) void gemm_f16(
    const __half* __restrict__ Ag, const __half* __restrict__ Bg,
    const float* __restrict__ bias,
    float* __restrict__ Cf, __half* __restrict__ Chh, int N)
{
    extern __shared__ char smc[];
    const uint32_t smbase = smem_u32(smc);

    const int tid  = threadIdx.x;
    const int w    = tid >> 5;
    const int lane = tid & 31;
    const int gr   = lane >> 2;
    const int lc   = lane & 3;
    const int bm   = blockIdx.y * 64;
    const int bn   = blockIdx.x * 128;

    const uint32_t aoff = (uint32_t)((lane & 15) * 144 + ((lane >> 4) << 4));
    const uint32_t boff = (uint32_t)((w * 32 + ((lane >> 4) << 3) + (lane & 7)) * 144
                                     + (((lane >> 3) & 1) << 4));

    auto issue_chunk = [&](int t, int buf) {
        const uint32_t bb = smbase + (uint32_t)(buf * STAGE_B);
        const int k0 = t * 64;
#pragma unroll
        for (int j = 0; j < 4; j++) {
            int i = tid + 128 * j;
            int r = i >> 3, ck = i & 7;
            cp16(bb + (uint32_t)(r * 144 + ck * 16),
                 Ag + (size_t)(bm + r) * GK + k0 + ck * 8);
        }
#pragma unroll
        for (int j = 0; j < 8; j++) {
            int i = tid + 128 * j;
            int r = i >> 3, ck = i & 7;
            cp16(bb + GA_B + (uint32_t)(r * 144 + ck * 16),
                 Bg + (size_t)(bn + r) * GK + k0 + ck * 8);
        }
        CP_COMMIT();
    };

    float acc[4][4][4];
#pragma unroll
    for (int mt = 0; mt < 4; mt++)
#pragma unroll
        for (int nt = 0; nt < 4; nt++)
#pragma unroll
            for (int r = 0; r < 4; r++) acc[mt][nt][r] = 0.f;

    issue_chunk(0, 0);
    issue_chunk(1, 1);

    for (int t = 0; t < NCHUNK; t++) {
        if (t + 1 < NCHUNK) { CP_WAIT1(); } else { CP_WAIT0(); }
        __syncthreads();

        {
            const uint32_t bufb = smbase + (uint32_t)((t & 1) * STAGE_B);
            const uint32_t a_b = bufb + aoff;
            const uint32_t b_b = bufb + GA_B + boff;

#pragma unroll
            for (int ks = 0; ks < 4; ks++) {
                const uint32_t kbb = (uint32_t)(ks * 32);
                uint32_t af[4][4], bf[4][2];
#pragma unroll
                for (int mt = 0; mt < 4; mt++)
                    ldm_x4(af[mt][0], af[mt][1], af[mt][2], af[mt][3],
                           a_b + (uint32_t)(mt * 2304) + kbb);
#pragma unroll
                for (int p = 0; p < 2; p++)
                    ldm_x4(bf[2 * p][0], bf[2 * p][1], bf[2 * p + 1][0], bf[2 * p + 1][1],
                           b_b + (uint32_t)(p * 2304) + kbb);
#pragma unroll
                for (int mt = 0; mt < 4; mt++)
#pragma unroll
                    for (int nt = 0; nt < 4; nt++)
                        mma_f16(acc[mt][nt][0], acc[mt][nt][1],
                                acc[mt][nt][2], acc[mt][nt][3],
                                af[mt][0], af[mt][1], af[mt][2], af[mt][3],
                                bf[nt][0], bf[nt][1]);
            }
        }
        __syncthreads();
        if (t + 2 < NCHUNK) issue_chunk(t + 2, t & 1);
    }

    // epilogue
#pragma unroll
    for (int nt = 0; nt < 4; nt++) {
        const int col = bn + w * 32 + nt * 8 + lc * 2;
        const float2 bj = *(const float2*)(bias + col);
#pragma unroll
        for (int mt = 0; mt < 4; mt++) {
            const int row0 = bm + mt * 16 + gr;
            float x0 = acc[mt][nt][0] + bj.x, y0 = acc[mt][nt][1] + bj.y;
            float x1 = acc[mt][nt][2] + bj.x, y1 = acc[mt][nt][3] + bj.y;
            if (HALF_OUT) {
                *(uint32_t*)(Chh + (size_t)row0 * N + col) = pkh(x0, y0);
                *(uint32_t*)(Chh + (size_t)(row0 + 8) * N + col) = pkh(x1, y1);
            } else {
                *(float2*)(Cf + (size_t)row0 * N + col) = make_float2(x0, y0);
                *(float2*)(Cf + (size_t)(row0 + 8) * N + col) = make_float2(x1, y1);
            }
        }
    }
}

// ---------------------------------------------------------------------------
// Flash attention (R11 configuration — the measured optimum):
// BQ=128, 256 thr (8 warps x 16 q-rows), cp.async double-buffered 64-token
// K/V tiles, V row-major + ldmatrix.trans.
// ---------------------------------------------------------------------------
#define FKST 104
#define FBUF_B (64 * FKST * 2)         // 13312 B per array
#define FSTAGE (2 * FBUF_B)            // 26624
#define FL_SMEM_BYTES (2 * FSTAGE)     // 53248

__global__ __launch_bounds__(256, 1) void flash_f16(
    const __half* __restrict__ qkvh, __half* __restrict__ atth)
{
    extern __shared__ char fsm[];
    const uint32_t smbase = smem_u32(fsm);

    const int qtp = 7 - (int)blockIdx.x;
    const int h   = blockIdx.y;
    const int b   = blockIdx.z;
    const int tid  = threadIdx.x;
    const int w    = tid >> 5;
    const int lane = tid & 31;
    const int gr   = lane >> 2;
    const int lc   = lane & 3;
    const int r0l  = w * 16 + gr;
    const int r1l  = r0l + 8;

    const int nkt = 2 * qtp + 2;
    const float rscale = 0.10206207261596577f;

    auto issue_tile = [&](int kt, int buf) {
        const uint32_t bb = smbase + (uint32_t)(buf * FSTAGE);
        const size_t rowbase = (size_t)(b * T_SEQ + kt * 64);
        const size_t koff = (size_t)C_EMB + h * HD;
        const size_t voff = (size_t)2 * C_EMB + h * HD;
#pragma unroll
        for (int j = 0; j < 3; j++) {
            int i = tid + 256 * j;
            int r = i / 12, ck = i % 12;
            const size_t so = (rowbase + r) * (3 * C_EMB) + ck * 8;
            uint32_t d = bb + (uint32_t)(r * 208 + ck * 16);
            cp16(d, qkvh + so + koff);
            cp16(d + FBUF_B, qkvh + so + voff);
        }
        CP_COMMIT();
    };

    issue_tile(0, 0);

    {   // stage Q into buf1 region
        const uint32_t qb = smbase + FSTAGE;
        const size_t rowbase = (size_t)(b * T_SEQ + qtp * 128);
        const size_t qoff = (size_t)h * HD;
#pragma unroll
        for (int j = 0; j < 6; j++) {
            int i = tid + 256 * j;
            int r = i / 12, ck = i % 12;
            const size_t so = (rowbase + r) * (3 * C_EMB) + qoff + ck * 8;
            *(uint4*)(fsm + (qb - smbase) + r * 208 + ck * 16) =
                *(const uint4*)(qkvh + so);
        }
    }
    __syncthreads();

    uint32_t Qf[6][4];
    {
        const uint32_t afl = (uint32_t)((lane & 15) * 208 + ((lane >> 4) << 4));
        const uint32_t qh_b = smbase + FSTAGE + (uint32_t)(w * 16 * 208) + afl;
#pragma unroll
        for (int ks = 0; ks < 6; ks++)
            ldm_x4(Qf[ks][0], Qf[ks][1], Qf[ks][2], Qf[ks][3], qh_b + ks * 32);
    }
    __syncthreads();
    issue_tile(1, 1);

    const uint32_t kfl = (uint32_t)((((lane >> 4) << 3) + (lane & 7)) * 208
                                    + ((lane >> 3) & 1) * 16);
    const uint32_t vfl = (uint32_t)((lane & 15) * 208 + ((lane >> 4) << 4));

    float accO[12][4];
#pragma unroll
    for (int nt = 0; nt < 12; nt++)
#pragma unroll
        for (int r = 0; r < 4; r++) accO[nt][r] = 0.f;
    float m0 = -1e30f, m1 = -1e30f, l0 = 0.f, l1 = 0.f;

    for (int kt = 0; kt < nkt; kt++) {
        if (kt + 1 < nkt) { CP_WAIT1(); } else { CP_WAIT0(); }
        __syncthreads();

        const uint32_t bb = smbase + (uint32_t)((kt & 1) * FSTAGE);
        const uint32_t k_b = bb + kfl;
        const uint32_t v_b = bb + FBUF_B + vfl;

        // ---- S = Q K^T ----
        float accS[8][4];
#pragma unroll
        for (int nt = 0; nt < 8; nt++)
#pragma unroll
            for (int r = 0; r < 4; r++) accS[nt][r] = 0.f;

#pragma unroll
        for (int ks = 0; ks < 6; ks++) {
            const uint32_t kxb = (uint32_t)(ks * 32);
            uint32_t bf[8][2];
#pragma unroll
            for (int p = 0; p < 4; p++)
                ldm_x4(bf[2 * p][0], bf[2 * p][1], bf[2 * p + 1][0], bf[2 * p + 1][1],
                       k_b + (uint32_t)(p * 16 * 208) + kxb);
#pragma unroll
            for (int nt = 0; nt < 8; nt++)
                mma_f16(accS[nt][0], accS[nt][1], accS[nt][2], accS[nt][3],
                        Qf[ks][0], Qf[ks][1], Qf[ks][2], Qf[ks][3],
                        bf[nt][0], bf[nt][1]);
        }

#pragma unroll
        for (int nt = 0; nt < 8; nt++)
#pragma unroll
            for (int r = 0; r < 4; r++) accS[nt][r] *= rscale;

        if (kt >= 2 * qtp) {
            const int qg0 = qtp * 128 + r0l;
            const int qg1 = qg0 + 8;
#pragma unroll
            for (int nt = 0; nt < 8; nt++) {
                int c0 = kt * 64 + nt * 8 + 2 * lc, c1 = c0 + 1;
                if (c0 > qg0) accS[nt][0] = -1e30f;
                if (c1 > qg0) accS[nt][1] = -1e30f;
                if (c0 > qg1) accS[nt][2] = -1e30f;
                if (c1 > qg1) accS[nt][3] = -1e30f;
            }
        }

        // ---- online softmax ----
        float mx0 = accS[0][0], mx1 = accS[0][2];
#pragma unroll
        for (int nt = 0; nt < 8; nt++) {
            mx0 = fmaxf(mx0, fmaxf(accS[nt][0], accS[nt][1]));
            mx1 = fmaxf(mx1, fmaxf(accS[nt][2], accS[nt][3]));
        }
        mx0 = fmaxf(mx0, __shfl_xor_sync(0xffffffffu, mx0, 1));
        mx0 = fmaxf(mx0, __shfl_xor_sync(0xffffffffu, mx0, 2));
        mx1 = fmaxf(mx1, __shfl_xor_sync(0xffffffffu, mx1, 1));
        mx1 = fmaxf(mx1, __shfl_xor_sync(0xffffffffu, mx1, 2));
        float nm0 = fmaxf(m0, mx0), nm1 = fmaxf(m1, mx1);
        float corr0 = __expf(m0 - nm0), corr1 = __expf(m1 - nm1);
        m0 = nm0; m1 = nm1;

        float rs0 = 0.f, rs1 = 0.f;
        uint32_t aP[4][4];
#pragma unroll
        for (int nt = 0; nt < 8; nt++) {
            float p0 = __expf(accS[nt][0] - m0);
            float p1 = __expf(accS[nt][1] - m0);
            float p2 = __expf(accS[nt][2] - m1);
            float p3 = __expf(accS[nt][3] - m1);
            rs0 += p0 + p1; rs1 += p2 + p3;
            const int i0 = (nt & 1) * 2;
            aP[nt >> 1][i0 + 0] = pkh(p0, p1);
            aP[nt >> 1][i0 + 1] = pkh(p2, p3);
        }
        rs0 += __shfl_xor_sync(0xffffffffu, rs0, 1);
        rs0 += __shfl_xor_sync(0xffffffffu, rs0, 2);
        rs1 += __shfl_xor_sync(0xffffffffu, rs1, 1);
        rs1 += __shfl_xor_sync(0xffffffffu, rs1, 2);
        l0 = l0 * corr0 + rs0;
        l1 = l1 * corr1 + rs1;

#pragma unroll
        for (int nt = 0; nt < 12; nt++) {
            accO[nt][0] *= corr0; accO[nt][1] *= corr0;
            accO[nt][2] *= corr1; accO[nt][3] *= corr1;
        }

        // ---- O += P V ----
#pragma unroll
        for (int kt2 = 0; kt2 < 4; kt2++) {
            const uint32_t toff = (uint32_t)(kt2 * 16 * 208);
            uint32_t a0 = aP[kt2][0], a1 = aP[kt2][1], a2 = aP[kt2][2], a3 = aP[kt2][3];
#pragma unroll
            for (int p = 0; p < 6; p++) {
                uint32_t v0, v1, v2, v3;
                ldm_x4_t(v0, v1, v2, v3, v_b + toff + (uint32_t)(p * 32));
                mma_f16(accO[2*p][0], accO[2*p][1], accO[2*p][2], accO[2*p][3],
                        a0, a1, a2, a3, v0, v1);
                mma_f16(accO[2*p+1][0], accO[2*p+1][1], accO[2*p+1][2], accO[2*p+1][3],
                        a0, a1, a2, a3, v2, v3);
            }
        }
        __syncthreads();
        if (kt + 2 < nkt) issue_tile(kt + 2, kt & 1);
    }

    // ---- epilogue: fp16 att ----
    const float inv0 = 1.f / l0;
    const float inv1 = 1.f / l1;
    const size_t grow0 = (size_t)(b * T_SEQ + qtp * 128 + r0l);
    const size_t grow1 = grow0 + 8;
#pragma unroll
    for (int nt = 0; nt < 12; nt++) {
        const int col = h * HD + nt * 8 + 2 * lc;
        *(uint32_t*)(atth + grow0 * C_EMB + col) = pkh(accO[nt][0] * inv0, accO[nt][1] * inv0);
        *(uint32_t*)(atth + grow1 * C_EMB + col) = pkh(accO[nt][2] * inv1, accO[nt][3] * inv1);
    }
}

// ---------------------------------------------------------------------------
// Launch
// ---------------------------------------------------------------------------
extern "C" void kernel_launch(void* const* d_in, const int* in_sizes, int n_in,
                              void* d_out, int out_size)
{
    (void)in_sizes; (void)n_in; (void)out_size;
    const float* x  = (const float*)d_in[0];
    const float* w1 = (const float*)d_in[1];
    const float* b1 = (const float*)d_in[2];
    const float* w2 = (const float*)d_in[3];
    const float* b2 = (const float*)d_in[4];
    float* out = (float*)d_out;

    __half *xh, *w1h, *w2h, *qh, *ah;
    cudaGetSymbolAddress((void**)&xh, g_xh);
    cudaGetSymbolAddress((void**)&w1h, g_w1h);
    cudaGetSymbolAddress((void**)&w2h, g_w2h);
    cudaGetSymbolAddress((void**)&qh, g_qkvh);
    cudaGetSymbolAddress((void**)&ah, g_atth);

    cudaFuncSetAttribute((const void*)gemm_f16<true>,
                         cudaFuncAttributeMaxDynamicSharedMemorySize, GEMM_SMEM_BYTES);
    cudaFuncSetAttribute((const void*)gemm_f16<false>,
                         cudaFuncAttributeMaxDynamicSharedMemorySize, GEMM_SMEM_BYTES);
    cudaFuncSetAttribute((const void*)flash_f16,
                         cudaFuncAttributeMaxDynamicSharedMemorySize, FL_SMEM_BYTES);

    // converts (single kernel)
    cvt_all<<<512, 256>>>(x,  xh,  M_ROWS * C_EMB / 4,
                          w1, w1h, 3 * C_EMB * C_EMB / 4,
                          w2, w2h, C_EMB * C_EMB / 4);

    // QKV projection -> fp16 qkv
    gemm_f16<true><<<dim3(3 * C_EMB / 128, M_ROWS / 64), 128, GEMM_SMEM_BYTES>>>(
        xh, w1h, b1, nullptr, qh, 3 * C_EMB);

    // Causal attention -> fp16 att (BQ=128)
    flash_f16<<<dim3(T_SEQ / 128, NH, BATCH), 256, FL_SMEM_BYTES>>>(qh, ah);

    // Output projection -> fp32 out
    gemm_f16<false><<<dim3(C_EMB / 128, M_ROWS / 64), 128, GEMM_SMEM_BYTES>>>(
        ah, w2h, b2, out, nullptr, C_EMB);
}

// round 14
// speedup vs baseline: 1.5357x; 1.0194x over previous
#include <cuda_runtime.h>
#include <cuda_fp16.h>
#include <math.h>
#include <stdint.h>

// Problem constants
#define BATCH 8
#define T_SEQ 1024
#define C_EMB 768
#define NH    8
#define HD    96
#define M_ROWS (BATCH * T_SEQ)   // 8192
#define GK    768

// ---------------------------------------------------------------------------
// Scratch: fp16 arrays
// ---------------------------------------------------------------------------
__device__ __half g_xh[(size_t)M_ROWS * C_EMB];
__device__ __half g_w1h[(size_t)3 * C_EMB * C_EMB];
__device__ __half g_w2h[(size_t)C_EMB * C_EMB];
__device__ __half g_qkvh[(size_t)M_ROWS * 3 * C_EMB];
__device__ __half g_atth[(size_t)M_ROWS * C_EMB];

// ---------------------------------------------------------------------------
// PTX helpers (baseline ISA at compute_103)
// ---------------------------------------------------------------------------
__device__ __forceinline__ uint32_t smem_u32(const void* p) {
    uint32_t a;
    asm("{ .reg .u64 t; cvta.to.shared.u64 t, %1; cvt.u32.u64 %0, t; }"
        : "=r"(a) : "l"(p));
    return a;
}
__device__ __forceinline__ void mma_f16(
    float& c0, float& c1, float& c2, float& c3,
    uint32_t a0, uint32_t a1, uint32_t a2, uint32_t a3,
    uint32_t b0, uint32_t b1)
{
    asm volatile(
        "mma.sync.aligned.m16n8k16.row.col.f32.f16.f16.f32 "
        "{%0,%1,%2,%3}, {%4,%5,%6,%7}, {%8,%9}, {%0,%1,%2,%3};"
        : "+f"(c0), "+f"(c1), "+f"(c2), "+f"(c3)
        : "r"(a0), "r"(a1), "r"(a2), "r"(a3), "r"(b0), "r"(b1));
}
__device__ __forceinline__ void ldm_x4(
    uint32_t& r0, uint32_t& r1, uint32_t& r2, uint32_t& r3, uint32_t saddr)
{
    asm volatile("ldmatrix.sync.aligned.m8n8.x4.shared.b16 {%0,%1,%2,%3}, [%4];"
        : "=r"(r0), "=r"(r1), "=r"(r2), "=r"(r3) : "r"(saddr));
}
__device__ __forceinline__ void ldm_x4_t(
    uint32_t& r0, uint32_t& r1, uint32_t& r2, uint32_t& r3, uint32_t saddr)
{
    asm volatile("ldmatrix.sync.aligned.m8n8.x4.trans.shared.b16 {%0,%1,%2,%3}, [%4];"
        : "=r"(r0), "=r"(r1), "=r"(r2), "=r"(r3) : "r"(saddr));
}
__device__ __forceinline__ void cp16(uint32_t dst, const void* src) {
    asm volatile("cp.async.cg.shared.global [%0], [%1], 16;"
        :: "r"(dst), "l"(src) : "memory");
}
#define CP_COMMIT() asm volatile("cp.async.commit_group;" ::: "memory")
#define CP_WAIT0()  asm volatile("cp.async.wait_group 0;" ::: "memory")
#define CP_WAIT1()  asm volatile("cp.async.wait_group 1;" ::: "memory")

__device__ __forceinline__ uint32_t pkh(float a, float b) {
    __half2 t = __floats2half2_rn(a, b);
    return *reinterpret_cast<uint32_t*>(&t);
}

// ---------------------------------------------------------------------------
// fp32 -> fp16 convert: all three inputs in one grid-stride kernel
// ---------------------------------------------------------------------------
__global__ void cvt_all(const float* __restrict__ s0, __half* __restrict__ h0, int n0,
                        const float* __restrict__ s1, __half* __restrict__ h1, int n1,
                        const float* __restrict__ s2, __half* __restrict__ h2, int n2)
{
    int total = n0 + n1 + n2;
    int i = blockIdx.x * blockDim.x + threadIdx.x;
    int stride = gridDim.x * blockDim.x;
    for (; i < total; i += stride) {
        const float* s; __half* h; int j;
        if (i < n0)            { s = s0; h = h0; j = i; }
        else if (i < n0 + n1)  { s = s1; h = h1; j = i - n0; }
        else                   { s = s2; h = h2; j = i - n0 - n1; }
        float4 v = ((const float4*)s)[j];
        ((uint2*)h)[j] = make_uint2(pkh(v.x, v.y), pkh(v.z, v.w));
    }
}

// ---------------------------------------------------------------------------
// Single-product fp16 GEMM (R11 config, measured at MMA-rate floor).
// CTA 64x128 (128 thr, 4 warps each 64x32), K chunked 64, cp.async x2.
// ---------------------------------------------------------------------------
#define GST 72
#define GA_B (64 * GST * 2)
#define GB_B (128 * GST * 2)
#define STAGE_B (GA_B + GB_B)
#define GEMM_SMEM_BYTES (2 * STAGE_B)
#define NCHUNK (GK / 64)

template <bool HALF_OUT>
__global__ __launch_bounds__(128, 4) void gemm_f16(
    const __half* __restrict__ Ag, const __half* __restrict__ Bg,
    const float* __restrict__ bias,
    float* __restrict__ Cf, __half* __restrict__ Chh, int N)
{
    extern __shared__ char smc[];
    const uint32_t smbase = smem_u32(smc);

    const int tid  = threadIdx.x;
    const int w    = tid >> 5;
    const int lane = tid & 31;
    const int gr   = lane >> 2;
    const int lc   = lane & 3;
    const int bm   = blockIdx.y * 64;
    const int bn   = blockIdx.x * 128;

    const uint32_t aoff = (uint32_t)((lane & 15) * 144 + ((lane >> 4) << 4));
    const uint32_t boff = (uint32_t)((w * 32 + ((lane >> 4) << 3) + (lane & 7)) * 144
                                     + (((lane >> 3) & 1) << 4));

    auto issue_chunk = [&](int t, int buf) {
        const uint32_t bb = smbase + (uint32_t)(buf * STAGE_B);
        const int k0 = t * 64;
#pragma unroll
        for (int j = 0; j < 4; j++) {
            int i = tid + 128 * j;
            int r = i >> 3, ck = i & 7;
            cp16(bb + (uint32_t)(r * 144 + ck * 16),
                 Ag + (size_t)(bm + r) * GK + k0 + ck * 8);
        }
#pragma unroll
        for (int j = 0; j < 8; j++) {
            int i = tid + 128 * j;
            int r = i >> 3, ck = i & 7;
            cp16(bb + GA_B + (uint32_t)(r * 144 + ck * 16),
                 Bg + (size_t)(bn + r) * GK + k0 + ck * 8);
        }
        CP_COMMIT();
    };

    float acc[4][4][4];
#pragma unroll
    for (int mt = 0; mt < 4; mt++)
#pragma unroll
        for (int nt = 0; nt < 4; nt++)
#pragma unroll
            for (int r = 0; r < 4; r++) acc[mt][nt][r] = 0.f;

    issue_chunk(0, 0);
    issue_chunk(1, 1);

    for (int t = 0; t < NCHUNK; t++) {
        if (t + 1 < NCHUNK) { CP_WAIT1(); } else { CP_WAIT0(); }
        __syncthreads();

        {
            const uint32_t bufb = smbase + (uint32_t)((t & 1) * STAGE_B);
            const uint32_t a_b = bufb + aoff;
            const uint32_t b_b = bufb + GA_B + boff;

#pragma unroll
            for (int ks = 0; ks < 4; ks++) {
                const uint32_t kbb = (uint32_t)(ks * 32);
                uint32_t af[4][4], bf[4][2];
#pragma unroll
                for (int mt = 0; mt < 4; mt++)
                    ldm_x4(af[mt][0], af[mt][1], af[mt][2], af[mt][3],
                           a_b + (uint32_t)(mt * 2304) + kbb);
#pragma unroll
                for (int p = 0; p < 2; p++)
                    ldm_x4(bf[2 * p][0], bf[2 * p][1], bf[2 * p + 1][0], bf[2 * p + 1][1],
                           b_b + (uint32_t)(p * 2304) + kbb);
#pragma unroll
                for (int mt = 0; mt < 4; mt++)
#pragma unroll
                    for (int nt = 0; nt < 4; nt++)
                        mma_f16(acc[mt][nt][0], acc[mt][nt][1],
                                acc[mt][nt][2], acc[mt][nt][3],
                                af[mt][0], af[mt][1], af[mt][2], af[mt][3],
                                bf[nt][0], bf[nt][1]);
            }
        }
        __syncthreads();
        if (t + 2 < NCHUNK) issue_chunk(t + 2, t & 1);
    }

    // epilogue
#pragma unroll
    for (int nt = 0; nt < 4; nt++) {
        const int col = bn + w * 32 + nt * 8 + lc * 2;
        const float2 bj = *(const float2*)(bias + col);
#pragma unroll
        for (int mt = 0; mt < 4; mt++) {
            const int row0 = bm + mt * 16 + gr;
            float x0 = acc[mt][nt][0] + bj.x, y0 = acc[mt][nt][1] + bj.y;
            float x1 = acc[mt][nt][2] + bj.x, y1 = acc[mt][nt][3] + bj.y;
            if (HALF_OUT) {
                *(uint32_t*)(Chh + (size_t)row0 * N + col) = pkh(x0, y0);
                *(uint32_t*)(Chh + (size_t)(row0 + 8) * N + col) = pkh(x1, y1);
            } else {
                *(float2*)(Cf + (size_t)row0 * N + col) = make_float2(x0, y0);
                *(float2*)(Cf + (size_t)(row0 + 8) * N + col) = make_float2(x1, y1);
            }
        }
    }
}

// ---------------------------------------------------------------------------
// Flash attention: BQ=128, 256 thr (8 warps x 16 q-rows), KT=128 k-tiles
// (half the tile visits of R11), cp.async double-buffered, exp2 softmax.
// ---------------------------------------------------------------------------
#define F2BUF (128 * 208)              // 26624 B per array (K or V)
#define F2STAGE (2 * F2BUF)            // 53248
#define FL_SMEM_BYTES (2 * F2STAGE)    // 106496

__global__ __launch_bounds__(256, 1) void flash_f16(
    const __half* __restrict__ qkvh, __half* __restrict__ atth)
{
    extern __shared__ char fsm[];
    const uint32_t smbase = smem_u32(fsm);

    const int qtp = 7 - (int)blockIdx.x;   // heavy tiles first
    const int h   = blockIdx.y;
    const int b   = blockIdx.z;
    const int tid  = threadIdx.x;
    const int w    = tid >> 5;
    const int lane = tid & 31;
    const int gr   = lane >> 2;
    const int lc   = lane & 3;
    const int r0l  = w * 16 + gr;          // local q row A (0..127)
    const int r1l  = r0l + 8;

    const int nkt = qtp + 1;               // 128-wide k tiles
    const float sc2 = 0.14724515f;         // (1/sqrt(96)) * log2(e)

    // stage = 128-token K + V tiles
    auto issue_tile = [&](int kt, int buf) {
        const uint32_t bb = smbase + (uint32_t)(buf * F2STAGE);
        const size_t rowbase = (size_t)(b * T_SEQ + kt * 128);
        const size_t koff = (size_t)C_EMB + h * HD;
        const size_t voff = (size_t)2 * C_EMB + h * HD;
#pragma unroll
        for (int j = 0; j < 6; j++) {      // 128 rows x 12 chunks
            int i = tid + 256 * j;
            int r = i / 12, ck = i % 12;
            const size_t so = (rowbase + r) * (3 * C_EMB) + ck * 8;
            uint32_t d = bb + (uint32_t)(r * 208 + ck * 16);
            cp16(d, qkvh + so + koff);             // K
            cp16(d + F2BUF, qkvh + so + voff);     // V
        }
        CP_COMMIT();
    };

    issue_tile(0, 0);

    {   // stage Q (128 rows x 208 B) into buf1's K region
        const uint32_t qb = smbase + F2STAGE;
        const size_t rowbase = (size_t)(b * T_SEQ + qtp * 128);
        const size_t qoff = (size_t)h * HD;
#pragma unroll
        for (int j = 0; j < 6; j++) {
            int i = tid + 256 * j;
            int r = i / 12, ck = i % 12;
            const size_t so = (rowbase + r) * (3 * C_EMB) + qoff + ck * 8;
            *(uint4*)(fsm + (qb - smbase) + r * 208 + ck * 16) =
                *(const uint4*)(qkvh + so);
        }
    }
    __syncthreads();

    uint32_t Qf[6][4];
    {
        const uint32_t afl = (uint32_t)((lane & 15) * 208 + ((lane >> 4) << 4));
        const uint32_t qh_b = smbase + F2STAGE + (uint32_t)(w * 16 * 208) + afl;
#pragma unroll
        for (int ks = 0; ks < 6; ks++)
            ldm_x4(Qf[ks][0], Qf[ks][1], Qf[ks][2], Qf[ks][3], qh_b + ks * 32);
    }
    __syncthreads();
    if (nkt > 1) issue_tile(1, 1);

    const uint32_t kfl = (uint32_t)((((lane >> 4) << 3) + (lane & 7)) * 208
                                    + ((lane >> 3) & 1) * 16);
    const uint32_t vfl = (uint32_t)((lane & 15) * 208 + ((lane >> 4) << 4));

    float accO[12][4];
#pragma unroll
    for (int nt = 0; nt < 12; nt++)
#pragma unroll
        for (int r = 0; r < 4; r++) accO[nt][r] = 0.f;
    float m0 = -1e30f, m1 = -1e30f, l0 = 0.f, l1 = 0.f;

    for (int kt = 0; kt < nkt; kt++) {
        if (kt + 1 < nkt) { CP_WAIT1(); } else { CP_WAIT0(); }
        __syncthreads();

        const uint32_t bb = smbase + (uint32_t)((kt & 1) * F2STAGE);
        const uint32_t k_b = bb + kfl;
        const uint32_t v_b = bb + F2BUF + vfl;

        // ---- S = Q K^T over 128 cols ----
        float accS[16][4];
#pragma unroll
        for (int nt = 0; nt < 16; nt++)
#pragma unroll
            for (int r = 0; r < 4; r++) accS[nt][r] = 0.f;

#pragma unroll
        for (int ks = 0; ks < 6; ks++) {
            const uint32_t kxb = (uint32_t)(ks * 32);
            uint32_t bf[16][2];
#pragma unroll
            for (int p = 0; p < 8; p++)
                ldm_x4(bf[2 * p][0], bf[2 * p][1], bf[2 * p + 1][0], bf[2 * p + 1][1],
                       k_b + (uint32_t)(p * 16 * 208) + kxb);
#pragma unroll
            for (int nt = 0; nt < 16; nt++)
                mma_f16(accS[nt][0], accS[nt][1], accS[nt][2], accS[nt][3],
                        Qf[ks][0], Qf[ks][1], Qf[ks][2], Qf[ks][3],
                        bf[nt][0], bf[nt][1]);
        }

        // logits scaled into log2 domain
#pragma unroll
        for (int nt = 0; nt < 16; nt++)
#pragma unroll
            for (int r = 0; r < 4; r++) accS[nt][r] *= sc2;

        if (kt == qtp) {   // diagonal 128x128 tile: local mask
#pragma unroll
            for (int nt = 0; nt < 16; nt++) {
                int c0 = nt * 8 + 2 * lc, c1 = c0 + 1;
                if (c0 > r0l) accS[nt][0] = -1e30f;
                if (c1 > r0l) accS[nt][1] = -1e30f;
                if (c0 > r1l) accS[nt][2] = -1e30f;
                if (c1 > r1l) accS[nt][3] = -1e30f;
            }
        }

        // ---- online softmax (base-2) ----
        float mx0 = accS[0][0], mx1 = accS[0][2];
#pragma unroll
        for (int nt = 0; nt < 16; nt++) {
            mx0 = fmaxf(mx0, fmaxf(accS[nt][0], accS[nt][1]));
            mx1 = fmaxf(mx1, fmaxf(accS[nt][2], accS[nt][3]));
        }
        mx0 = fmaxf(mx0, __shfl_xor_sync(0xffffffffu, mx0, 1));
        mx0 = fmaxf(mx0, __shfl_xor_sync(0xffffffffu, mx0, 2));
        mx1 = fmaxf(mx1, __shfl_xor_sync(0xffffffffu, mx1, 1));
        mx1 = fmaxf(mx1, __shfl_xor_sync(0xffffffffu, mx1, 2));
        float nm0 = fmaxf(m0, mx0), nm1 = fmaxf(m1, mx1);
        float corr0 = exp2f(m0 - nm0), corr1 = exp2f(m1 - nm1);
        m0 = nm0; m1 = nm1;

        float rs0 = 0.f, rs1 = 0.f;
        uint32_t aP[8][4];
#pragma unroll
        for (int nt = 0; nt < 16; nt++) {
            float p0 = exp2f(accS[nt][0] - m0);
            float p1 = exp2f(accS[nt][1] - m0);
            float p2 = exp2f(accS[nt][2] - m1);
            float p3 = exp2f(accS[nt][3] - m1);
            rs0 += p0 + p1; rs1 += p2 + p3;
            const int i0 = (nt & 1) * 2;
            aP[nt >> 1][i0 + 0] = pkh(p0, p1);
            aP[nt >> 1][i0 + 1] = pkh(p2, p3);
        }
        rs0 += __shfl_xor_sync(0xffffffffu, rs0, 1);
        rs0 += __shfl_xor_sync(0xffffffffu, rs0, 2);
        rs1 += __shfl_xor_sync(0xffffffffu, rs1, 1);
        rs1 += __shfl_xor_sync(0xffffffffu, rs1, 2);
        l0 = l0 * corr0 + rs0;
        l1 = l1 * corr1 + rs1;

#pragma unroll
        for (int nt = 0; nt < 12; nt++) {
            accO[nt][0] *= corr0; accO[nt][1] *= corr0;
            accO[nt][2] *= corr1; accO[nt][3] *= corr1;
        }

        // ---- O += P V (8 x k16 steps over 128 tokens) ----
#pragma unroll
        for (int kt2 = 0; kt2 < 8; kt2++) {
            const uint32_t toff = (uint32_t)(kt2 * 16 * 208);
            uint32_t a0 = aP[kt2][0], a1 = aP[kt2][1], a2 = aP[kt2][2], a3 = aP[kt2][3];
#pragma unroll
            for (int p = 0; p < 6; p++) {
                uint32_t v0, v1, v2, v3;
                ldm_x4_t(v0, v1, v2, v3, v_b + toff + (uint32_t)(p * 32));
                mma_f16(accO[2*p][0], accO[2*p][1], accO[2*p][2], accO[2*p][3],
                        a0, a1, a2, a3, v0, v1);
                mma_f16(accO[2*p+1][0], accO[2*p+1][1], accO[2*p+1][2], accO[2*p+1][3],
                        a0, a1, a2, a3, v2, v3);
            }
        }
        __syncthreads();
        if (kt + 2 < nkt) issue_tile(kt + 2, kt & 1);
    }

    // ---- epilogue: fp16 att ----
    const float inv0 = 1.f / l0;
    const float inv1 = 1.f / l1;
    const size_t grow0 = (size_t)(b * T_SEQ + qtp * 128 + r0l);
    const size_t grow1 = grow0 + 8;
#pragma unroll
    for (int nt = 0; nt < 12; nt++) {
        const int col = h * HD + nt * 8 + 2 * lc;
        *(uint32_t*)(atth + grow0 * C_EMB + col) = pkh(accO[nt][0] * inv0, accO[nt][1] * inv0);
        *(uint32_t*)(atth + grow1 * C_EMB + col) = pkh(accO[nt][2] * inv1, accO[nt][3] * inv1);
    }
}

// ---------------------------------------------------------------------------
// Launch
// ---------------------------------------------------------------------------
extern "C" void kernel_launch(void* const* d_in, const int* in_sizes, int n_in,
                              void* d_out, int out_size)
{
    (void)in_sizes; (void)n_in; (void)out_size;
    const float* x  = (const float*)d_in[0];
    const float* w1 = (const float*)d_in[1];
    const float* b1 = (const float*)d_in[2];
    const float* w2 = (const float*)d_in[3];
    const float* b2 = (const float*)d_in[4];
    float* out = (float*)d_out;

    __half *xh, *w1h, *w2h, *qh, *ah;
    cudaGetSymbolAddress((void**)&xh, g_xh);
    cudaGetSymbolAddress((void**)&w1h, g_w1h);
    cudaGetSymbolAddress((void**)&w2h, g_w2h);
    cudaGetSymbolAddress((void**)&qh, g_qkvh);
    cudaGetSymbolAddress((void**)&ah, g_atth);

    cudaFuncSetAttribute((const void*)gemm_f16<true>,
                         cudaFuncAttributeMaxDynamicSharedMemorySize, GEMM_SMEM_BYTES);
    cudaFuncSetAttribute((const void*)gemm_f16<false>,
                         cudaFuncAttributeMaxDynamicSharedMemorySize, GEMM_SMEM_BYTES);
    cudaFuncSetAttribute((const void*)flash_f16,
                         cudaFuncAttributeMaxDynamicSharedMemorySize, FL_SMEM_BYTES);

    // converts (single kernel)
    cvt_all<<<512, 256>>>(x,  xh,  M_ROWS * C_EMB / 4,
                          w1, w1h, 3 * C_EMB * C_EMB / 4,
                          w2, w2h, C_EMB * C_EMB / 4);

    // QKV projection -> fp16 qkv
    gemm_f16<true><<<dim3(3 * C_EMB / 128, M_ROWS / 64), 128, GEMM_SMEM_BYTES>>>(
        xh, w1h, b1, nullptr, qh, 3 * C_EMB);

    // Causal attention -> fp16 att (BQ=128, KT=128)
    flash_f16<<<dim3(T_SEQ / 128, NH, BATCH), 256, FL_SMEM_BYTES>>>(qh, ah);

    // Output projection -> fp32 out
    gemm_f16<false><<<dim3(C_EMB / 128, M_ROWS / 64), 128, GEMM_SMEM_BYTES>>>(
        ah, w2h, b2, out, nullptr, C_EMB);
}

// round 15
// speedup vs baseline: 1.5398x; 1.0027x over previous
#include <cuda_runtime.h>
#include <cuda_fp16.h>
#include <math.h>
#include <stdint.h>

// Problem constants
#define BATCH 8
#define T_SEQ 1024
#define C_EMB 768
#define NH    8
#define HD    96
#define M_ROWS (BATCH * T_SEQ)   // 8192
#define GK    768

// ---------------------------------------------------------------------------
// Scratch: fp16 arrays
// ---------------------------------------------------------------------------
__device__ __half g_xh[(size_t)M_ROWS * C_EMB];
__device__ __half g_w1h[(size_t)3 * C_EMB * C_EMB];
__device__ __half g_w2h[(size_t)C_EMB * C_EMB];
__device__ __half g_qkvh[(size_t)M_ROWS * 3 * C_EMB];
__device__ __half g_atth[(size_t)M_ROWS * C_EMB];

// ---------------------------------------------------------------------------
// PTX helpers (baseline ISA at compute_103)
// ---------------------------------------------------------------------------
__device__ __forceinline__ uint32_t smem_u32(const void* p) {
    uint32_t a;
    asm("{ .reg .u64 t; cvta.to.shared.u64 t, %1; cvt.u32.u64 %0, t; }"
        : "=r"(a) : "l"(p));
    return a;
}
__device__ __forceinline__ void mma_f16(
    float& c0, float& c1, float& c2, float& c3,
    uint32_t a0, uint32_t a1, uint32_t a2, uint32_t a3,
    uint32_t b0, uint32_t b1)
{
    asm volatile(
        "mma.sync.aligned.m16n8k16.row.col.f32.f16.f16.f32 "
        "{%0,%1,%2,%3}, {%4,%5,%6,%7}, {%8,%9}, {%0,%1,%2,%3};"
        : "+f"(c0), "+f"(c1), "+f"(c2), "+f"(c3)
        : "r"(a0), "r"(a1), "r"(a2), "r"(a3), "r"(b0), "r"(b1));
}
__device__ __forceinline__ void ldm_x4(
    uint32_t& r0, uint32_t& r1, uint32_t& r2, uint32_t& r3, uint32_t saddr)
{
    asm volatile("ldmatrix.sync.aligned.m8n8.x4.shared.b16 {%0,%1,%2,%3}, [%4];"
        : "=r"(r0), "=r"(r1), "=r"(r2), "=r"(r3) : "r"(saddr));
}
__device__ __forceinline__ void ldm_x4_t(
    uint32_t& r0, uint32_t& r1, uint32_t& r2, uint32_t& r3, uint32_t saddr)
{
    asm volatile("ldmatrix.sync.aligned.m8n8.x4.trans.shared.b16 {%0,%1,%2,%3}, [%4];"
        : "=r"(r0), "=r"(r1), "=r"(r2), "=r"(r3) : "r"(saddr));
}
__device__ __forceinline__ void cp16(uint32_t dst, const void* src) {
    asm volatile("cp.async.cg.shared.global [%0], [%1], 16;"
        :: "r"(dst), "l"(src) : "memory");
}
#define CP_COMMIT() asm volatile("cp.async.commit_group;" ::: "memory")
#define CP_WAIT0()  asm volatile("cp.async.wait_group 0;" ::: "memory")
#define CP_WAIT1()  asm volatile("cp.async.wait_group 1;" ::: "memory")
#define CP_WAIT2()  asm volatile("cp.async.wait_group 2;" ::: "memory")

__device__ __forceinline__ uint32_t pkh(float a, float b) {
    __half2 t = __floats2half2_rn(a, b);
    return *reinterpret_cast<uint32_t*>(&t);
}

// ---------------------------------------------------------------------------
// fp32 -> fp16 convert: all three inputs in one grid-stride kernel
// ---------------------------------------------------------------------------
__global__ void cvt_all(const float* __restrict__ s0, __half* __restrict__ h0, int n0,
                        const float* __restrict__ s1, __half* __restrict__ h1, int n1,
                        const float* __restrict__ s2, __half* __restrict__ h2, int n2)
{
    int total = n0 + n1 + n2;
    int i = blockIdx.x * blockDim.x + threadIdx.x;
    int stride = gridDim.x * blockDim.x;
    for (; i < total; i += stride) {
        const float* s; __half* h; int j;
        if (i < n0)            { s = s0; h = h0; j = i; }
        else if (i < n0 + n1)  { s = s1; h = h1; j = i - n0; }
        else                   { s = s2; h = h2; j = i - n0 - n1; }
        float4 v = ((const float4*)s)[j];
        ((uint2*)h)[j] = make_uint2(pkh(v.x, v.y), pkh(v.z, v.w));
    }
}

// ---------------------------------------------------------------------------
// Single-product fp16 GEMM (R11 config, measured at MMA-rate floor).
// CTA 64x128 (128 thr, 4 warps each 64x32), K chunked 64, cp.async x2.
// ---------------------------------------------------------------------------
#define GST 72
#define GA_B (64 * GST * 2)
#define GB_B (128 * GST * 2)
#define STAGE_B (GA_B + GB_B)
#define GEMM_SMEM_BYTES (2 * STAGE_B)
#define NCHUNK (GK / 64)

template <bool HALF_OUT>
__global__ __launch_bounds__(128, 4) void gemm_f16(
    const __half* __restrict__ Ag, const __half* __restrict__ Bg,
    const float* __restrict__ bias,
    float* __restrict__ Cf, __half* __restrict__ Chh, int N)
{
    extern __shared__ char smc[];
    const uint32_t smbase = smem_u32(smc);

    const int tid  = threadIdx.x;
    const int w    = tid >> 5;
    const int lane = tid & 31;
    const int gr   = lane >> 2;
    const int lc   = lane & 3;
    const int bm   = blockIdx.y * 64;
    const int bn   = blockIdx.x * 128;

    const uint32_t aoff = (uint32_t)((lane & 15) * 144 + ((lane >> 4) << 4));
    const uint32_t boff = (uint32_t)((w * 32 + ((lane >> 4) << 3) + (lane & 7)) * 144
                                     + (((lane >> 3) & 1) << 4));

    auto issue_chunk = [&](int t, int buf) {
        const uint32_t bb = smbase + (uint32_t)(buf * STAGE_B);
        const int k0 = t * 64;
#pragma unroll
        for (int j = 0; j < 4; j++) {
            int i = tid + 128 * j;
            int r = i >> 3, ck = i & 7;
            cp16(bb + (uint32_t)(r * 144 + ck * 16),
                 Ag + (size_t)(bm + r) * GK + k0 + ck * 8);
        }
#pragma unroll
        for (int j = 0; j < 8; j++) {
            int i = tid + 128 * j;
            int r = i >> 3, ck = i & 7;
            cp16(bb + GA_B + (uint32_t)(r * 144 + ck * 16),
                 Bg + (size_t)(bn + r) * GK + k0 + ck * 8);
        }
        CP_COMMIT();
    };

    float acc[4][4][4];
#pragma unroll
    for (int mt = 0; mt < 4; mt++)
#pragma unroll
        for (int nt = 0; nt < 4; nt++)
#pragma unroll
            for (int r = 0; r < 4; r++) acc[mt][nt][r] = 0.f;

    issue_chunk(0, 0);
    issue_chunk(1, 1);

    for (int t = 0; t < NCHUNK; t++) {
        if (t + 1 < NCHUNK) { CP_WAIT1(); } else { CP_WAIT0(); }
        __syncthreads();

        {
            const uint32_t bufb = smbase + (uint32_t)((t & 1) * STAGE_B);
            const uint32_t a_b = bufb + aoff;
            const uint32_t b_b = bufb + GA_B + boff;

#pragma unroll
            for (int ks = 0; ks < 4; ks++) {
                const uint32_t kbb = (uint32_t)(ks * 32);
                uint32_t af[4][4], bf[4][2];
#pragma unroll
                for (int mt = 0; mt < 4; mt++)
                    ldm_x4(af[mt][0], af[mt][1], af[mt][2], af[mt][3],
                           a_b + (uint32_t)(mt * 2304) + kbb);
#pragma unroll
                for (int p = 0; p < 2; p++)
                    ldm_x4(bf[2 * p][0], bf[2 * p][1], bf[2 * p + 1][0], bf[2 * p + 1][1],
                           b_b + (uint32_t)(p * 2304) + kbb);
#pragma unroll
                for (int mt = 0; mt < 4; mt++)
#pragma unroll
                    for (int nt = 0; nt < 4; nt++)
                        mma_f16(acc[mt][nt][0], acc[mt][nt][1],
                                acc[mt][nt][2], acc[mt][nt][3],
                                af[mt][0], af[mt][1], af[mt][2], af[mt][3],
                                bf[nt][0], bf[nt][1]);
            }
        }
        __syncthreads();
        if (t + 2 < NCHUNK) issue_chunk(t + 2, t & 1);
    }

    // epilogue
#pragma unroll
    for (int nt = 0; nt < 4; nt++) {
        const int col = bn + w * 32 + nt * 8 + lc * 2;
        const float2 bj = *(const float2*)(bias + col);
#pragma unroll
        for (int mt = 0; mt < 4; mt++) {
            const int row0 = bm + mt * 16 + gr;
            float x0 = acc[mt][nt][0] + bj.x, y0 = acc[mt][nt][1] + bj.y;
            float x1 = acc[mt][nt][2] + bj.x, y1 = acc[mt][nt][3] + bj.y;
            if (HALF_OUT) {
                *(uint32_t*)(Chh + (size_t)row0 * N + col) = pkh(x0, y0);
                *(uint32_t*)(Chh + (size_t)(row0 + 8) * N + col) = pkh(x1, y1);
            } else {
                *(float2*)(Cf + (size_t)row0 * N + col) = make_float2(x0, y0);
                *(float2*)(Cf + (size_t)(row0 + 8) * N + col) = make_float2(x1, y1);
            }
        }
    }
}

// ---------------------------------------------------------------------------
// Flash attention: BQ=128, 256 thr (8 warps x 16 q-rows), KT=128 k-tiles,
// THREE-stage cp.async pipeline (two tiles always in flight), exp2 softmax.
// smem = 3 x 53248 = 159744 B, 1 CTA/SM.
// ---------------------------------------------------------------------------
#define F2BUF (128 * 208)              // 26624 B per array (K or V)
#define F2STAGE (2 * F2BUF)            // 53248
#define FL_SMEM_BYTES (3 * F2STAGE)    // 159744

__global__ __launch_bounds__(256, 1) void flash_f16(
    const __half* __restrict__ qkvh, __half* __restrict__ atth)
{
    extern __shared__ char fsm[];
    const uint32_t smbase = smem_u32(fsm);

    const int qtp = 7 - (int)blockIdx.x;   // heavy tiles first
    const int h   = blockIdx.y;
    const int b   = blockIdx.z;
    const int tid  = threadIdx.x;
    const int w    = tid >> 5;
    const int lane = tid & 31;
    const int gr   = lane >> 2;
    const int lc   = lane & 3;
    const int r0l  = w * 16 + gr;          // local q row A (0..127)
    const int r1l  = r0l + 8;

    const int nkt = qtp + 1;               // 128-wide k tiles
    const float sc2 = 0.14724515f;         // (1/sqrt(96)) * log2(e)

    auto issue_tile = [&](int kt, int buf) {
        const uint32_t bb = smbase + (uint32_t)(buf * F2STAGE);
        const size_t rowbase = (size_t)(b * T_SEQ + kt * 128);
        const size_t koff = (size_t)C_EMB + h * HD;
        const size_t voff = (size_t)2 * C_EMB + h * HD;
#pragma unroll
        for (int j = 0; j < 6; j++) {      // 128 rows x 12 chunks
            int i = tid + 256 * j;
            int r = i / 12, ck = i % 12;
            const size_t so = (rowbase + r) * (3 * C_EMB) + ck * 8;
            uint32_t d = bb + (uint32_t)(r * 208 + ck * 16);
            cp16(d, qkvh + so + koff);             // K
            cp16(d + F2BUF, qkvh + so + voff);     // V
        }
        CP_COMMIT();
    };

    issue_tile(0, 0);
    if (nkt > 1) issue_tile(1, 1);

    {   // stage Q (128 rows x 208 B) into buf2's K region
        const uint32_t qb = smbase + 2 * F2STAGE;
        const size_t rowbase = (size_t)(b * T_SEQ + qtp * 128);
        const size_t qoff = (size_t)h * HD;
#pragma unroll
        for (int j = 0; j < 6; j++) {
            int i = tid + 256 * j;
            int r = i / 12, ck = i % 12;
            const size_t so = (rowbase + r) * (3 * C_EMB) + qoff + ck * 8;
            *(uint4*)(fsm + (qb - smbase) + r * 208 + ck * 16) =
                *(const uint4*)(qkvh + so);
        }
    }
    __syncthreads();

    uint32_t Qf[6][4];
    {
        const uint32_t afl = (uint32_t)((lane & 15) * 208 + ((lane >> 4) << 4));
        const uint32_t qh_b = smbase + 2 * F2STAGE + (uint32_t)(w * 16 * 208) + afl;
#pragma unroll
        for (int ks = 0; ks < 6; ks++)
            ldm_x4(Qf[ks][0], Qf[ks][1], Qf[ks][2], Qf[ks][3], qh_b + ks * 32);
    }
    __syncthreads();                       // buf2 free before tile 2 lands there
    if (nkt > 2) issue_tile(2, 2);

    const uint32_t kfl = (uint32_t)((((lane >> 4) << 3) + (lane & 7)) * 208
                                    + ((lane >> 3) & 1) * 16);
    const uint32_t vfl = (uint32_t)((lane & 15) * 208 + ((lane >> 4) << 4));

    float accO[12][4];
#pragma unroll
    for (int nt = 0; nt < 12; nt++)
#pragma unroll
        for (int r = 0; r < 4; r++) accO[nt][r] = 0.f;
    float m0 = -1e30f, m1 = -1e30f, l0 = 0.f, l1 = 0.f;

    int buf = 0;
    for (int kt = 0; kt < nkt; kt++) {
        const int rem = nkt - 1 - kt;      // tiles committed beyond kt
        if (rem >= 2)      { CP_WAIT2(); }
        else if (rem == 1) { CP_WAIT1(); }
        else               { CP_WAIT0(); }
        __syncthreads();

        const uint32_t bb = smbase + (uint32_t)(buf * F2STAGE);
        const uint32_t k_b = bb + kfl;
        const uint32_t v_b = bb + F2BUF + vfl;

        // ---- S = Q K^T over 128 cols ----
        float accS[16][4];
#pragma unroll
        for (int nt = 0; nt < 16; nt++)
#pragma unroll
            for (int r = 0; r < 4; r++) accS[nt][r] = 0.f;

#pragma unroll
        for (int ks = 0; ks < 6; ks++) {
            const uint32_t kxb = (uint32_t)(ks * 32);
            uint32_t bf[16][2];
#pragma unroll
            for (int p = 0; p < 8; p++)
                ldm_x4(bf[2 * p][0], bf[2 * p][1], bf[2 * p + 1][0], bf[2 * p + 1][1],
                       k_b + (uint32_t)(p * 16 * 208) + kxb);
#pragma unroll
            for (int nt = 0; nt < 16; nt++)
                mma_f16(accS[nt][0], accS[nt][1], accS[nt][2], accS[nt][3],
                        Qf[ks][0], Qf[ks][1], Qf[ks][2], Qf[ks][3],
                        bf[nt][0], bf[nt][1]);
        }

        // logits scaled into log2 domain
#pragma unroll
        for (int nt = 0; nt < 16; nt++)
#pragma unroll
            for (int r = 0; r < 4; r++) accS[nt][r] *= sc2;

        if (kt == qtp) {   // diagonal 128x128 tile: local mask
#pragma unroll
            for (int nt = 0; nt < 16; nt++) {
                int c0 = nt * 8 + 2 * lc, c1 = c0 + 1;
                if (c0 > r0l) accS[nt][0] = -1e30f;
                if (c1 > r0l) accS[nt][1] = -1e30f;
                if (c0 > r1l) accS[nt][2] = -1e30f;
                if (c1 > r1l) accS[nt][3] = -1e30f;
            }
        }

        // ---- online softmax (base-2) ----
        float mx0 = accS[0][0], mx1 = accS[0][2];
#pragma unroll
        for (int nt = 0; nt < 16; nt++) {
            mx0 = fmaxf(mx0, fmaxf(accS[nt][0], accS[nt][1]));
            mx1 = fmaxf(mx1, fmaxf(accS[nt][2], accS[nt][3]));
        }
        mx0 = fmaxf(mx0, __shfl_xor_sync(0xffffffffu, mx0, 1));
        mx0 = fmaxf(mx0, __shfl_xor_sync(0xffffffffu, mx0, 2));
        mx1 = fmaxf(mx1, __shfl_xor_sync(0xffffffffu, mx1, 1));
        mx1 = fmaxf(mx1, __shfl_xor_sync(0xffffffffu, mx1, 2));
        float nm0 = fmaxf(m0, mx0), nm1 = fmaxf(m1, mx1);
        float corr0 = exp2f(m0 - nm0), corr1 = exp2f(m1 - nm1);
        m0 = nm0; m1 = nm1;

        float rs0 = 0.f, rs1 = 0.f;
        uint32_t aP[8][4];
#pragma unroll
        for (int nt = 0; nt < 16; nt++) {
            float p0 = exp2f(accS[nt][0] - m0);
            float p1 = exp2f(accS[nt][1] - m0);
            float p2 = exp2f(accS[nt][2] - m1);
            float p3 = exp2f(accS[nt][3] - m1);
            rs0 += p0 + p1; rs1 += p2 + p3;
            const int i0 = (nt & 1) * 2;
            aP[nt >> 1][i0 + 0] = pkh(p0, p1);
            aP[nt >> 1][i0 + 1] = pkh(p2, p3);
        }
        rs0 += __shfl_xor_sync(0xffffffffu, rs0, 1);
        rs0 += __shfl_xor_sync(0xffffffffu, rs0, 2);
        rs1 += __shfl_xor_sync(0xffffffffu, rs1, 1);
        rs1 += __shfl_xor_sync(0xffffffffu, rs1, 2);
        l0 = l0 * corr0 + rs0;
        l1 = l1 * corr1 + rs1;

#pragma unroll
        for (int nt = 0; nt < 12; nt++) {
            accO[nt][0] *= corr0; accO[nt][1] *= corr0;
            accO[nt][2] *= corr1; accO[nt][3] *= corr1;
        }

        // ---- O += P V (8 x k16 steps over 128 tokens) ----
#pragma unroll
        for (int kt2 = 0; kt2 < 8; kt2++) {
            const uint32_t toff = (uint32_t)(kt2 * 16 * 208);
            uint32_t a0 = aP[kt2][0], a1 = aP[kt2][1], a2 = aP[kt2][2], a3 = aP[kt2][3];
#pragma unroll
            for (int p = 0; p < 6; p++) {
                uint32_t v0, v1, v2, v3;
                ldm_x4_t(v0, v1, v2, v3, v_b + toff + (uint32_t)(p * 32));
                mma_f16(accO[2*p][0], accO[2*p][1], accO[2*p][2], accO[2*p][3],
                        a0, a1, a2, a3, v0, v1);
                mma_f16(accO[2*p+1][0], accO[2*p+1][1], accO[2*p+1][2], accO[2*p+1][3],
                        a0, a1, a2, a3, v2, v3);
            }
        }
        __syncthreads();
        if (kt + 3 < nkt) issue_tile(kt + 3, buf);   // reuse freed buffer
        buf = (buf == 2) ? 0 : buf + 1;
    }

    // ---- epilogue: fp16 att ----
    const float inv0 = 1.f / l0;
    const float inv1 = 1.f / l1;
    const size_t grow0 = (size_t)(b * T_SEQ + qtp * 128 + r0l);
    const size_t grow1 = grow0 + 8;
#pragma unroll
    for (int nt = 0; nt < 12; nt++) {
        const int col = h * HD + nt * 8 + 2 * lc;
        *(uint32_t*)(atth + grow0 * C_EMB + col) = pkh(accO[nt][0] * inv0, accO[nt][1] * inv0);
        *(uint32_t*)(atth + grow1 * C_EMB + col) = pkh(accO[nt][2] * inv1, accO[nt][3] * inv1);
    }
}

// ---------------------------------------------------------------------------
// Launch
// ---------------------------------------------------------------------------
extern "C" void kernel_launch(void* const* d_in, const int* in_sizes, int n_in,
                              void* d_out, int out_size)
{
    (void)in_sizes; (void)n_in; (void)out_size;
    const float* x  = (const float*)d_in[0];
    const float* w1 = (const float*)d_in[1];
    const float* b1 = (const float*)d_in[2];
    const float* w2 = (const float*)d_in[3];
    const float* b2 = (const float*)d_in[4];
    float* out = (float*)d_out;

    __half *xh, *w1h, *w2h, *qh, *ah;
    cudaGetSymbolAddress((void**)&xh, g_xh);
    cudaGetSymbolAddress((void**)&w1h, g_w1h);
    cudaGetSymbolAddress((void**)&w2h, g_w2h);
    cudaGetSymbolAddress((void**)&qh, g_qkvh);
    cudaGetSymbolAddress((void**)&ah, g_atth);

    cudaFuncSetAttribute((const void*)gemm_f16<true>,
                         cudaFuncAttributeMaxDynamicSharedMemorySize, GEMM_SMEM_BYTES);
    cudaFuncSetAttribute((const void*)gemm_f16<false>,
                         cudaFuncAttributeMaxDynamicSharedMemorySize, GEMM_SMEM_BYTES);
    cudaFuncSetAttribute((const void*)flash_f16,
                         cudaFuncAttributeMaxDynamicSharedMemorySize, FL_SMEM_BYTES);

    // converts (single kernel)
    cvt_all<<<512, 256>>>(x,  xh,  M_ROWS * C_EMB / 4,
                          w1, w1h, 3 * C_EMB * C_EMB / 4,
                          w2, w2h, C_EMB * C_EMB / 4);

    // QKV projection -> fp16 qkv
    gemm_f16<true><<<dim3(3 * C_EMB / 128, M_ROWS / 64), 128, GEMM_SMEM_BYTES>>>(
        xh, w1h, b1, nullptr, qh, 3 * C_EMB);

    // Causal attention -> fp16 att (BQ=128, KT=128, 3-stage pipeline)
    flash_f16<<<dim3(T_SEQ / 128, NH, BATCH), 256, FL_SMEM_BYTES>>>(qh, ah);

    // Output projection -> fp32 out
    gemm_f16<false><<<dim3(C_EMB / 128, M_ROWS / 64), 128, GEMM_SMEM_BYTES>>>(
        ah, w2h, b2, out, nullptr, C_EMB);
}